// round 3
// baseline (speedup 1.0000x reference)
#include <cuda_runtime.h>

#define NN 50000
#define EE 800000

// Scratch (allocation-free: __device__ globals)
__device__ float g_deg[NN];
__device__ float g_dinv[NN];
__device__ float g_h1[NN * 64];
__device__ float g_h2[NN * 64];
__device__ float g_agg[NN * 64];
__device__ float g_t[NN * 32];

// ---------------------------------------------------------------------------
__global__ void k_zero(float* p, int n) {
    int i = blockIdx.x * blockDim.x + threadIdx.x;
    if (i < n) p[i] = 0.f;
}

__global__ void k_deg(const int* __restrict__ ei) {
    int e = blockIdx.x * blockDim.x + threadIdx.x;
    if (e >= EE) return;
    unsigned d = (unsigned)ei[EE + e];
    if (d < NN) atomicAdd(&g_deg[d], 1.0f);
}

__global__ void k_dinv() {
    int i = blockIdx.x * blockDim.x + threadIdx.x;
    if (i < NN) g_dinv[i] = 1.0f / fmaxf(g_deg[i], 1.0f);
}

// Layer 1 scatter: aggregate raw 5-channel features
__global__ void k_scatter5(const int* __restrict__ ei,
                           const float* __restrict__ x) {
    int e = blockIdx.x * blockDim.x + threadIdx.x;
    if (e >= EE) return;
    unsigned s = (unsigned)ei[e];
    unsigned d = (unsigned)ei[EE + e];
    if (s >= NN || d >= NN) return;
#pragma unroll
    for (int c = 0; c < 5; c++)
        atomicAdd(&g_agg[d * 5 + c], x[s * 5 + c]);
}

// Layer 1 combine: h1 = relu(mean5 @ W1l^T + b1 + x @ W1r^T)
__global__ void k_combine1(const float* __restrict__ x,
                           const float* __restrict__ W1l,
                           const float* __restrict__ b1,
                           const float* __restrict__ W1r) {
    int t = blockIdx.x * blockDim.x + threadIdx.x;
    if (t >= NN * 64) return;
    int i = t >> 6, j = t & 63;
    float invd = g_dinv[i];
    float acc = __ldg(&b1[j]);
#pragma unroll
    for (int c = 0; c < 5; c++) {
        acc = fmaf(g_agg[i * 5 + c] * invd, __ldg(&W1l[j * 5 + c]), acc);
        acc = fmaf(x[i * 5 + c], __ldg(&W1r[j * 5 + c]), acc);
    }
    g_h1[t] = fmaxf(acc, 0.f);
}

// 64-channel edge scatter (layer 2): one thread per (edge, channel)
__global__ void k_scatter64(const int* __restrict__ ei) {
    long long idx = (long long)blockIdx.x * blockDim.x + threadIdx.x;
    if (idx >= (long long)EE * 64) return;
    int e = (int)(idx >> 6), c = (int)(idx & 63);
    unsigned s = (unsigned)ei[e];
    unsigned d = (unsigned)ei[EE + e];
    if (s >= NN || d >= NN) return;
    atomicAdd(&g_agg[d * 64 + c], g_h1[s * 64 + c]);
}

// 64->64 combine with weights staged (transposed) in shared memory.
// Block = 256 threads = 4 nodes x 64 output channels. 50000 % 4 == 0.
__global__ void k_combine64(const float* __restrict__ Wl,
                            const float* __restrict__ b,
                            const float* __restrict__ Wr) {
    __shared__ float sWl[64 * 64];  // transposed: sWl[c*64 + j]
    __shared__ float sWr[64 * 64];
    __shared__ float sIn[4][64];
    __shared__ float sAg[4][64];
    int tid = threadIdx.x;
    for (int k = tid; k < 4096; k += 256) {
        int j = k >> 6, c = k & 63;
        sWl[c * 64 + j] = Wl[k];
        sWr[c * 64 + j] = Wr[k];
    }
    int g = tid >> 6, j = tid & 63;
    int node = blockIdx.x * 4 + g;
    float invd = g_dinv[node];
    sIn[g][j] = g_h1[node * 64 + j];
    sAg[g][j] = g_agg[node * 64 + j] * invd;
    __syncthreads();

    float acc = __ldg(&b[j]);
#pragma unroll
    for (int c = 0; c < 64; c++) {
        acc = fmaf(sAg[g][c], sWl[c * 64 + j], acc);
        acc = fmaf(sIn[g][c], sWr[c * 64 + j], acc);
    }
    g_h2[node * 64 + j] = fmaxf(acc, 0.f);
}

// Layer 3 pre-transform: t = h2 @ W3l^T  (N x 32).
// Block = 256 threads = 8 nodes x 32 output channels. 50000 % 8 == 0.
__global__ void k_t3(const float* __restrict__ W3l) {
    __shared__ float sW[64 * 32];  // transposed: sW[c*32 + j]
    __shared__ float sIn[8][64];
    int tid = threadIdx.x;
    for (int k = tid; k < 2048; k += 256) {
        int j = k >> 6, c = k & 63;
        sW[c * 32 + j] = W3l[k];
    }
    for (int k = tid; k < 512; k += 256) {
        int gg = k >> 6, c = k & 63;
        sIn[gg][c] = g_h2[(blockIdx.x * 8 + gg) * 64 + c];
    }
    __syncthreads();
    int g = tid >> 5, j = tid & 31;
    int node = blockIdx.x * 8 + g;
    float acc = 0.f;
#pragma unroll
    for (int c = 0; c < 64; c++)
        acc = fmaf(sIn[g][c], sW[c * 32 + j], acc);
    g_t[node * 32 + j] = acc;
}

// 32-channel edge scatter (layer 3)
__global__ void k_scatter32(const int* __restrict__ ei) {
    long long idx = (long long)blockIdx.x * blockDim.x + threadIdx.x;
    if (idx >= (long long)EE * 32) return;
    int e = (int)(idx >> 5), c = (int)(idx & 31);
    unsigned s = (unsigned)ei[e];
    unsigned d = (unsigned)ei[EE + e];
    if (s >= NN || d >= NN) return;
    atomicAdd(&g_agg[d * 32 + c], g_t[s * 32 + c]);
}

// Final: out = inv_deg * agg32 + b3 + h2 @ W3r^T
__global__ void k_final(const float* __restrict__ b3,
                        const float* __restrict__ W3r,
                        float* __restrict__ out) {
    __shared__ float sW[64 * 32];  // transposed W3r
    __shared__ float sIn[8][64];
    int tid = threadIdx.x;
    for (int k = tid; k < 2048; k += 256) {
        int j = k >> 6, c = k & 63;
        sW[c * 32 + j] = W3r[k];
    }
    for (int k = tid; k < 512; k += 256) {
        int gg = k >> 6, c = k & 63;
        sIn[gg][c] = g_h2[(blockIdx.x * 8 + gg) * 64 + c];
    }
    __syncthreads();
    int g = tid >> 5, j = tid & 31;
    int node = blockIdx.x * 8 + g;
    float invd = g_dinv[node];
    float acc = __ldg(&b3[j]) + g_agg[node * 32 + j] * invd;
#pragma unroll
    for (int c = 0; c < 64; c++)
        acc = fmaf(sIn[g][c], sW[c * 32 + j], acc);
    out[node * 32 + j] = acc;
}

// ---------------------------------------------------------------------------
extern "C" void kernel_launch(void* const* d_in, const int* in_sizes, int n_in,
                              void* d_out, int out_size) {
    const float* x   = (const float*)d_in[0];
    const int*   ei  = (const int*)d_in[1];   // JAX default: int64 -> int32
    const float* W1l = (const float*)d_in[2];
    const float* b1  = (const float*)d_in[3];
    const float* W1r = (const float*)d_in[4];
    const float* W2l = (const float*)d_in[5];
    const float* b2  = (const float*)d_in[6];
    const float* W2r = (const float*)d_in[7];
    const float* W3l = (const float*)d_in[8];
    const float* b3  = (const float*)d_in[9];
    const float* W3r = (const float*)d_in[10];
    float* out = (float*)d_out;

    // Host-visible addresses of device globals (for the zero kernels only).
    void* p_deg = nullptr;
    void* p_agg = nullptr;
    cudaGetSymbolAddress(&p_deg, g_deg);
    cudaGetSymbolAddress(&p_agg, g_agg);

    const int T = 256;
    // degree (recomputed every call: deterministic, graph-capturable)
    k_zero<<<(NN + T - 1) / T, T>>>((float*)p_deg, NN);
    k_zero<<<(NN * 5 + T - 1) / T, T>>>((float*)p_agg, NN * 5);
    k_deg<<<(EE + T - 1) / T, T>>>(ei);
    k_dinv<<<(NN + T - 1) / T, T>>>();

    // layer 1
    k_scatter5<<<(EE + T - 1) / T, T>>>(ei, x);
    k_combine1<<<(NN * 64 + T - 1) / T, T>>>(x, W1l, b1, W1r);

    // layer 2
    k_zero<<<(NN * 64 + T - 1) / T, T>>>((float*)p_agg, NN * 64);
    k_scatter64<<<(int)(((long long)EE * 64 + T - 1) / T), T>>>(ei);
    k_combine64<<<NN / 4, T>>>(W2l, b2, W2r);

    // layer 3 (transform-then-aggregate: scatter 32 ch instead of 64)
    k_t3<<<NN / 8, T>>>(W3l);
    k_zero<<<(NN * 32 + T - 1) / T, T>>>((float*)p_agg, NN * 32);
    k_scatter32<<<(int)(((long long)EE * 32 + T - 1) / T), T>>>(ei);
    k_final<<<NN / 8, T>>>(b3, W3r, out);
}

// round 4
// speedup vs baseline: 1.1929x; 1.1929x over previous
#include <cuda_runtime.h>

#define NN 50000
#define EE 800000

// Scratch (allocation-free: __device__ globals; zero-initialized at load)
__device__ float g_deg[NN];
__device__ float g_dinv[NN];
__device__ float g_h1[NN * 64];
__device__ float g_h2[NN * 64];
__device__ float g_agg[NN * 64];   // reused: stride-8 (layer1) / 64 (layer2) / 32 (layer3)
__device__ float g_t[NN * 32];

__device__ __forceinline__ void red_add_v4(float* addr, float4 v) {
    asm volatile("red.global.add.v4.f32 [%0], {%1,%2,%3,%4};"
                 :: "l"(addr), "f"(v.x), "f"(v.y), "f"(v.z), "f"(v.w)
                 : "memory");
}

// ---------------------------------------------------------------------------
__global__ void k_zero4(float4* p, int n4) {
    int i = blockIdx.x * blockDim.x + threadIdx.x;
    if (i < n4) p[i] = make_float4(0.f, 0.f, 0.f, 0.f);
}

__global__ void k_dinv() {
    int i = blockIdx.x * blockDim.x + threadIdx.x;
    if (i < NN) g_dinv[i] = 1.0f / fmaxf(g_deg[i], 1.0f);
}

// Layer 1 scatter (+degree): agg8[d*8 + 0..4] += x[s], deg[d] += 1
__global__ void k_scatter5deg(const int* __restrict__ ei,
                              const float* __restrict__ x) {
    int e = blockIdx.x * blockDim.x + threadIdx.x;
    if (e >= EE) return;
    unsigned s = (unsigned)ei[e];
    unsigned d = (unsigned)ei[EE + e];
    if (s >= NN || d >= NN) return;
    const float* xr = x + s * 5;
    float4 v = make_float4(__ldg(xr), __ldg(xr + 1), __ldg(xr + 2), __ldg(xr + 3));
    red_add_v4(&g_agg[d * 8], v);
    atomicAdd(&g_agg[d * 8 + 4], __ldg(xr + 4));
    atomicAdd(&g_deg[d], 1.0f);
}

// Layer 1 combine: h1 = relu(mean5 @ W1l^T + b1 + x @ W1r^T); re-zeroes agg8.
__global__ void k_combine1(const float* __restrict__ x,
                           const float* __restrict__ W1l,
                           const float* __restrict__ b1,
                           const float* __restrict__ W1r) {
    int t = blockIdx.x * blockDim.x + threadIdx.x;
    if (t >= NN * 64) return;
    int i = t >> 6, j = t & 63;
    float invd = g_dinv[i];
    float acc = __ldg(&b1[j]);
#pragma unroll
    for (int c = 0; c < 5; c++) {
        acc = fmaf(g_agg[i * 8 + c] * invd, __ldg(&W1l[j * 5 + c]), acc);
        acc = fmaf(__ldg(&x[i * 5 + c]), __ldg(&W1r[j * 5 + c]), acc);
    }
    __syncthreads();                     // all reads of agg8 done (nodes are block-local)
    if (j < 8) g_agg[i * 8 + j] = 0.f;   // ready for scatter64
    g_h1[t] = fmaxf(acc, 0.f);
}

// Layer 2 scatter: 16 float4-reds per edge (64 ch). EE*16 threads.
__global__ void k_scatter64v(const int* __restrict__ ei) {
    int idx = blockIdx.x * blockDim.x + threadIdx.x;   // < EE*16 = 12.8M
    int e = idx >> 4, c = idx & 15;
    if (e >= EE) return;
    unsigned s = (unsigned)ei[e];
    unsigned d = (unsigned)ei[EE + e];
    if (s >= NN || d >= NN) return;
    float4 v = ((const float4*)g_h1)[s * 16 + c];
    red_add_v4(&g_agg[d * 64 + c * 4], v);
}

// 64->64 combine, weights transposed in smem; re-zeroes agg64.
// Block = 256 threads = 4 nodes x 64 channels.
__global__ void k_combine64(const float* __restrict__ Wl,
                            const float* __restrict__ b,
                            const float* __restrict__ Wr) {
    __shared__ float sWl[64 * 64];
    __shared__ float sWr[64 * 64];
    __shared__ float sIn[4][64];
    __shared__ float sAg[4][64];
    int tid = threadIdx.x;
    for (int k = tid; k < 4096; k += 256) {
        int j = k >> 6, c = k & 63;
        sWl[c * 64 + j] = Wl[k];
        sWr[c * 64 + j] = Wr[k];
    }
    int g = tid >> 6, j = tid & 63;
    int node = blockIdx.x * 4 + g;
    float invd = g_dinv[node];
    sIn[g][j] = g_h1[node * 64 + j];
    sAg[g][j] = g_agg[node * 64 + j] * invd;
    __syncthreads();
    g_agg[node * 64 + j] = 0.f;          // ready for scatter32

    float acc = __ldg(&b[j]);
#pragma unroll
    for (int c = 0; c < 64; c++) {
        acc = fmaf(sAg[g][c], sWl[c * 64 + j], acc);
        acc = fmaf(sIn[g][c], sWr[c * 64 + j], acc);
    }
    g_h2[node * 64 + j] = fmaxf(acc, 0.f);
}

// Layer 3 pre-transform: t = h2 @ W3l^T. Block = 8 nodes x 32 channels.
__global__ void k_t3(const float* __restrict__ W3l) {
    __shared__ float sW[64 * 32];
    __shared__ float sIn[8][64];
    int tid = threadIdx.x;
    for (int k = tid; k < 2048; k += 256) {
        int j = k >> 6, c = k & 63;
        sW[c * 32 + j] = W3l[k];
    }
    for (int k = tid; k < 512; k += 256) {
        int gg = k >> 6, c = k & 63;
        sIn[gg][c] = g_h2[(blockIdx.x * 8 + gg) * 64 + c];
    }
    __syncthreads();
    int g = tid >> 5, j = tid & 31;
    int node = blockIdx.x * 8 + g;
    float acc = 0.f;
#pragma unroll
    for (int c = 0; c < 64; c++)
        acc = fmaf(sIn[g][c], sW[c * 32 + j], acc);
    g_t[node * 32 + j] = acc;
}

// Layer 3 scatter: 8 float4-reds per edge (32 ch). EE*8 threads.
__global__ void k_scatter32v(const int* __restrict__ ei) {
    int idx = blockIdx.x * blockDim.x + threadIdx.x;   // < EE*8 = 6.4M
    int e = idx >> 3, c = idx & 7;
    if (e >= EE) return;
    unsigned s = (unsigned)ei[e];
    unsigned d = (unsigned)ei[EE + e];
    if (s >= NN || d >= NN) return;
    float4 v = ((const float4*)g_t)[s * 8 + c];
    red_add_v4(&g_agg[d * 32 + c * 4], v);
}

// Final: out = inv_deg * agg32 + b3 + h2 @ W3r^T
__global__ void k_final(const float* __restrict__ b3,
                        const float* __restrict__ W3r,
                        float* __restrict__ out) {
    __shared__ float sW[64 * 32];
    __shared__ float sIn[8][64];
    int tid = threadIdx.x;
    for (int k = tid; k < 2048; k += 256) {
        int j = k >> 6, c = k & 63;
        sW[c * 32 + j] = W3r[k];
    }
    for (int k = tid; k < 512; k += 256) {
        int gg = k >> 6, c = k & 63;
        sIn[gg][c] = g_h2[(blockIdx.x * 8 + gg) * 64 + c];
    }
    __syncthreads();
    int g = tid >> 5, j = tid & 31;
    int node = blockIdx.x * 8 + g;
    float invd = g_dinv[node];
    float acc = __ldg(&b3[j]) + g_agg[node * 32 + j] * invd;
#pragma unroll
    for (int c = 0; c < 64; c++)
        acc = fmaf(sIn[g][c], sW[c * 32 + j], acc);
    out[node * 32 + j] = acc;
}

// ---------------------------------------------------------------------------
extern "C" void kernel_launch(void* const* d_in, const int* in_sizes, int n_in,
                              void* d_out, int out_size) {
    const float* x   = (const float*)d_in[0];
    const int*   ei  = (const int*)d_in[1];   // int64 in reference -> int32 on device
    const float* W1l = (const float*)d_in[2];
    const float* b1  = (const float*)d_in[3];
    const float* W1r = (const float*)d_in[4];
    const float* W2l = (const float*)d_in[5];
    const float* b2  = (const float*)d_in[6];
    const float* W2r = (const float*)d_in[7];
    const float* W3l = (const float*)d_in[8];
    const float* b3  = (const float*)d_in[9];
    const float* W3r = (const float*)d_in[10];
    float* out = (float*)d_out;

    void* p_deg = nullptr;
    void* p_agg = nullptr;
    cudaGetSymbolAddress(&p_deg, g_deg);
    cudaGetSymbolAddress(&p_agg, g_agg);

    const int T = 256;
    // Restore invariant: agg[0 .. NN*32) may be dirty from previous replay;
    // the rest of agg is left zero by k_combine64. deg recomputed each call.
    k_zero4<<<(NN * 32 / 4 + T - 1) / T, T>>>((float4*)p_agg, NN * 32 / 4);
    k_zero4<<<(NN / 4 + T - 1) / T, T>>>((float4*)p_deg, NN / 4);

    // layer 1 (+degree)
    k_scatter5deg<<<(EE + T - 1) / T, T>>>(ei, x);
    k_dinv<<<(NN + T - 1) / T, T>>>();
    k_combine1<<<(NN * 64 + T - 1) / T, T>>>(x, W1l, b1, W1r);

    // layer 2
    k_scatter64v<<<(EE * 16 + T - 1) / T, T>>>(ei);
    k_combine64<<<NN / 4, T>>>(W2l, b2, W2r);

    // layer 3 (transform-then-aggregate: scatter 32 ch instead of 64)
    k_t3<<<NN / 8, T>>>(W3l);
    k_scatter32v<<<(EE * 8 + T - 1) / T, T>>>(ei);
    k_final<<<NN / 8, T>>>(b3, W3r, out);
}

// round 5
// speedup vs baseline: 2.8171x; 2.3616x over previous
#include <cuda_runtime.h>

#define NN 50000
#define EE 800000

// Scratch (allocation-free: __device__ globals)
__device__ float g_dinv[NN];
__device__ float g_h1[NN * 64];
__device__ float g_h2[NN * 64];
__device__ float g_agg[NN * 64];   // layer1: stride-8 atomic target; layer2/3: plain-store mean
__device__ float g_t[NN * 32];
__device__ int   g_degi[NN];
__device__ int   g_cur[NN];
__device__ int   g_rp[NN];         // CSR row start (exclusive prefix of deg)
__device__ int   g_bsum[256];
__device__ int   g_boff[256];
__device__ int   g_csr[EE];        // src node per CSR slot

__device__ __forceinline__ void red_add_v4(float* addr, float4 v) {
    asm volatile("red.global.add.v4.f32 [%0], {%1,%2,%3,%4};"
                 :: "l"(addr), "f"(v.x), "f"(v.y), "f"(v.z), "f"(v.w)
                 : "memory");
}

// ---------------------------------------------------------------------------
// Per-call init: zero the layer-1 atomic region + int counters.
__global__ void k_init() {
    int i = blockIdx.x * blockDim.x + threadIdx.x;
    if (i < NN * 8) g_agg[i] = 0.f;
    if (i < NN) { g_degi[i] = 0; g_cur[i] = 0; }
}

__global__ void k_degi(const int* __restrict__ ei) {
    int e = blockIdx.x * blockDim.x + threadIdx.x;
    if (e < EE) atomicAdd(&g_degi[ei[EE + e]], 1);
}

// Exclusive scan of degrees: per-block scan -> block sums -> add offsets.
__global__ void k_scanA() {
    __shared__ int sm[256];
    int i = blockIdx.x * 256 + threadIdx.x;
    int d = (i < NN) ? g_degi[i] : 0;
    int v = d;
    sm[threadIdx.x] = v; __syncthreads();
#pragma unroll
    for (int o = 1; o < 256; o <<= 1) {
        int t = (threadIdx.x >= o) ? sm[threadIdx.x - o] : 0;
        __syncthreads();
        v += t; sm[threadIdx.x] = v;
        __syncthreads();
    }
    if (i < NN) g_rp[i] = v - d;               // exclusive within block
    if (threadIdx.x == 255) g_bsum[blockIdx.x] = v;
}
__global__ void k_scanB(int nblk) {
    __shared__ int sm[256];
    int t = threadIdx.x;
    int d = (t < nblk) ? g_bsum[t] : 0;
    int v = d;
    sm[t] = v; __syncthreads();
#pragma unroll
    for (int o = 1; o < 256; o <<= 1) {
        int u = (t >= o) ? sm[t - o] : 0;
        __syncthreads();
        v += u; sm[t] = v;
        __syncthreads();
    }
    if (t < nblk) g_boff[t] = v - d;           // exclusive block offset
}
__global__ void k_scanC() {
    int i = blockIdx.x * 256 + threadIdx.x;
    if (i < NN) g_rp[i] += g_boff[i >> 8];
}

__global__ void k_fill(const int* __restrict__ ei) {
    int e = blockIdx.x * blockDim.x + threadIdx.x;
    if (e >= EE) return;
    int s = ei[e], d = ei[EE + e];
    int p = atomicAdd(&g_cur[d], 1);
    g_csr[g_rp[d] + p] = s;
}

__global__ void k_dinv() {
    int i = blockIdx.x * blockDim.x + threadIdx.x;
    if (i < NN) g_dinv[i] = 1.0f / fmaxf((float)g_degi[i], 1.0f);
}

// Layer 1 scatter: agg8[d*8 + 0..4] += x[s]  (cheap: 5 channels)
__global__ void k_scatter5(const int* __restrict__ ei,
                           const float* __restrict__ x) {
    int e = blockIdx.x * blockDim.x + threadIdx.x;
    if (e >= EE) return;
    int s = ei[e], d = ei[EE + e];
    const float* xr = x + s * 5;
    float4 v = make_float4(__ldg(xr), __ldg(xr + 1), __ldg(xr + 2), __ldg(xr + 3));
    red_add_v4(&g_agg[d * 8], v);
    atomicAdd(&g_agg[d * 8 + 4], __ldg(xr + 4));
}

// Layer 1 combine: h1 = relu(mean5 @ W1l^T + b1 + x @ W1r^T)
__global__ void k_combine1(const float* __restrict__ x,
                           const float* __restrict__ W1l,
                           const float* __restrict__ b1,
                           const float* __restrict__ W1r) {
    int t = blockIdx.x * blockDim.x + threadIdx.x;
    if (t >= NN * 64) return;
    int i = t >> 6, j = t & 63;
    float invd = g_dinv[i];
    float acc = __ldg(&b1[j]);
#pragma unroll
    for (int c = 0; c < 5; c++) {
        acc = fmaf(g_agg[i * 8 + c] * invd, __ldg(&W1l[j * 5 + c]), acc);
        acc = fmaf(__ldg(&x[i * 5 + c]), __ldg(&W1r[j * 5 + c]), acc);
    }
    g_h1[t] = fmaxf(acc, 0.f);
}

// Layer 2 aggregation: warp per node, CSR gather, no atomics.
// Lane handles 2 channels (float2); per neighbor the warp reads one 256B row.
__global__ void k_agg64() {
    int w = (blockIdx.x * blockDim.x + threadIdx.x) >> 5;
    if (w >= NN) return;
    int lane = threadIdx.x & 31;
    int beg = g_rp[w], deg = g_degi[w];
    const float2* h1v = (const float2*)g_h1;
    float ax = 0.f, ay = 0.f;
    for (int base = 0; base < deg; base += 32) {
        int n = min(32, deg - base);
        int idx = (base + lane < deg) ? g_csr[beg + base + lane] : 0;
#pragma unroll 8
        for (int k = 0; k < n; k++) {
            int s = __shfl_sync(0xffffffffu, idx, k);
            float2 v = h1v[s * 32 + lane];
            ax += v.x; ay += v.y;
        }
    }
    float invd = g_dinv[w];
    ((float2*)g_agg)[w * 32 + lane] = make_float2(ax * invd, ay * invd);
}

// 64->64 combine; 40 nodes per block (weights staged once per block).
__global__ void k_combine64(const float* __restrict__ Wl,
                            const float* __restrict__ b,
                            const float* __restrict__ Wr) {
    __shared__ float sWl[64 * 64];
    __shared__ float sWr[64 * 64];
    __shared__ float sIn[4][64];
    __shared__ float sAg[4][64];
    int tid = threadIdx.x;
    for (int k = tid; k < 4096; k += 256) {
        int j = k >> 6, c = k & 63;
        sWl[c * 64 + j] = Wl[k];
        sWr[c * 64 + j] = Wr[k];
    }
    int g = tid >> 6, j = tid & 63;
    float bj = __ldg(&b[j]);
    for (int it = 0; it < 10; it++) {
        int node = (blockIdx.x * 10 + it) * 4 + g;
        __syncthreads();
        sIn[g][j] = g_h1[node * 64 + j];
        sAg[g][j] = g_agg[node * 64 + j];   // already mean-scaled
        __syncthreads();
        float acc = bj;
#pragma unroll
        for (int c = 0; c < 64; c++) {
            acc = fmaf(sAg[g][c], sWl[c * 64 + j], acc);
            acc = fmaf(sIn[g][c], sWr[c * 64 + j], acc);
        }
        g_h2[node * 64 + j] = fmaxf(acc, 0.f);
    }
}

// Layer 3 pre-transform: t = h2 @ W3l^T. 80 nodes per block.
__global__ void k_t3(const float* __restrict__ W3l) {
    __shared__ float sW[64 * 32];
    __shared__ float sIn[8][64];
    int tid = threadIdx.x;
    for (int k = tid; k < 2048; k += 256) {
        int j = k >> 6, c = k & 63;
        sW[c * 32 + j] = W3l[k];
    }
    int g = tid >> 5, j = tid & 31;
    for (int it = 0; it < 10; it++) {
        int node0 = (blockIdx.x * 10 + it) * 8;
        __syncthreads();
        for (int k = tid; k < 512; k += 256) {
            int gg = k >> 6, c = k & 63;
            sIn[gg][c] = g_h2[(node0 + gg) * 64 + c];
        }
        __syncthreads();
        float acc = 0.f;
#pragma unroll
        for (int c = 0; c < 64; c++)
            acc = fmaf(sIn[g][c], sW[c * 32 + j], acc);
        g_t[(node0 + g) * 32 + j] = acc;
    }
}

// Layer 3 aggregation: warp per node, lane = channel. 128B row per neighbor.
__global__ void k_agg32() {
    int w = (blockIdx.x * blockDim.x + threadIdx.x) >> 5;
    if (w >= NN) return;
    int lane = threadIdx.x & 31;
    int beg = g_rp[w], deg = g_degi[w];
    float acc = 0.f;
    for (int base = 0; base < deg; base += 32) {
        int n = min(32, deg - base);
        int idx = (base + lane < deg) ? g_csr[beg + base + lane] : 0;
#pragma unroll 8
        for (int k = 0; k < n; k++) {
            int s = __shfl_sync(0xffffffffu, idx, k);
            acc += g_t[s * 32 + lane];
        }
    }
    g_agg[w * 32 + lane] = acc * g_dinv[w];
}

// Final: out = mean32 + b3 + h2 @ W3r^T. 80 nodes per block.
__global__ void k_final(const float* __restrict__ b3,
                        const float* __restrict__ W3r,
                        float* __restrict__ out) {
    __shared__ float sW[64 * 32];
    __shared__ float sIn[8][64];
    int tid = threadIdx.x;
    for (int k = tid; k < 2048; k += 256) {
        int j = k >> 6, c = k & 63;
        sW[c * 32 + j] = W3r[k];
    }
    int g = tid >> 5, j = tid & 31;
    float bj = __ldg(&b3[j]);
    for (int it = 0; it < 10; it++) {
        int node0 = (blockIdx.x * 10 + it) * 8;
        __syncthreads();
        for (int k = tid; k < 512; k += 256) {
            int gg = k >> 6, c = k & 63;
            sIn[gg][c] = g_h2[(node0 + gg) * 64 + c];
        }
        __syncthreads();
        int node = node0 + g;
        float acc = bj + g_agg[node * 32 + j];
#pragma unroll
        for (int c = 0; c < 64; c++)
            acc = fmaf(sIn[g][c], sW[c * 32 + j], acc);
        out[node * 32 + j] = acc;
    }
}

// ---------------------------------------------------------------------------
extern "C" void kernel_launch(void* const* d_in, const int* in_sizes, int n_in,
                              void* d_out, int out_size) {
    const float* x   = (const float*)d_in[0];
    const int*   ei  = (const int*)d_in[1];
    const float* W1l = (const float*)d_in[2];
    const float* b1  = (const float*)d_in[3];
    const float* W1r = (const float*)d_in[4];
    const float* W2l = (const float*)d_in[5];
    const float* b2  = (const float*)d_in[6];
    const float* W2r = (const float*)d_in[7];
    const float* W3l = (const float*)d_in[8];
    const float* b3  = (const float*)d_in[9];
    const float* W3r = (const float*)d_in[10];
    float* out = (float*)d_out;

    const int T = 256;
    const int SCAN_BLKS = (NN + 255) / 256;   // 196

    k_init<<<(NN * 8 + T - 1) / T, T>>>();
    // CSR build
    k_degi<<<(EE + T - 1) / T, T>>>(ei);
    k_scanA<<<SCAN_BLKS, 256>>>();
    k_scanB<<<1, 256>>>(SCAN_BLKS);
    k_scanC<<<SCAN_BLKS, 256>>>();
    k_fill<<<(EE + T - 1) / T, T>>>(ei);
    k_dinv<<<(NN + T - 1) / T, T>>>();

    // layer 1
    k_scatter5<<<(EE + T - 1) / T, T>>>(ei, x);
    k_combine1<<<(NN * 64 + T - 1) / T, T>>>(x, W1l, b1, W1r);

    // layer 2 (gather aggregation, no atomics)
    k_agg64<<<(NN * 32 + T - 1) / T, T>>>();
    k_combine64<<<NN / 40, T>>>(W2l, b2, W2r);   // 1250 blocks

    // layer 3 (transform-then-aggregate)
    k_t3<<<NN / 80, T>>>(W3l);                   // 625 blocks
    k_agg32<<<(NN * 32 + T - 1) / T, T>>>();
    k_final<<<NN / 80, T>>>(b3, W3r, out);       // 625 blocks
}